// round 2
// baseline (speedup 1.0000x reference)
#include <cuda_runtime.h>
#include <math.h>

#define Bt 8
#define Nn 4096
#define Dd 1024
#define Pp 16
#define ITERS 3
#define TN 128
#define DK 128
#define NT (Nn/TN)
#define XSTRIDE (DK+4)
#define LOG2PI 1.8378770664093453f

// persistent state / scratch (no allocations allowed)
__device__ float g_A[Bt*Dd*Pp];     // [b][d][p] = mu * invSigma
__device__ float g_I[Bt*Dd*Pp];     // [b][d][p] = invSigma
__device__ float g_cst[Bt*Pp];      // log pi - 0.5*(d log2pi + sum log S + sum mu^2/S)
__device__ float g_pi[Bt*Pp];
__device__ float g_mu[Bt*Pp*Dd];
__device__ float g_Sg[Bt*Pp*Dd];
__device__ float g_mV[Pp*Dd];       // V + m*m
__device__ float g_wsum[Bt*Pp];
__device__ float g_wx[Bt*Pp*Dd];
__device__ float g_wxx[Bt*Pp*Dd];

__global__ void k_init(const float* __restrict__ m, const float* __restrict__ V_) {
    int i = blockIdx.x * blockDim.x + threadIdx.x;
    if (i < Pp*Dd) {
        float v = 0.1f * log1pf(expf(V_[i]));   // EPS * softplus(V_)
        float mm = m[i];
        g_mV[i] = v + mm*mm;
        #pragma unroll
        for (int b = 0; b < Bt; b++) {
            g_mu[b*Pp*Dd + i] = mm;
            g_Sg[b*Pp*Dd + i] = v;
            g_wx[b*Pp*Dd + i] = 0.f;
            g_wxx[b*Pp*Dd + i] = 0.f;
        }
    }
    if (i < Bt*Pp) { g_pi[i] = 1.0f/Pp; g_wsum[i] = 0.f; }
}

__global__ void k_prep() {
    int b = blockIdx.x / Pp, p = blockIdx.x % Pp;
    __shared__ float red[256];
    float acc = 0.f;
    for (int d = threadIdx.x; d < Dd; d += 256) {
        float S  = g_Sg[(b*Pp + p)*Dd + d];
        float mu = g_mu[(b*Pp + p)*Dd + d];
        float inv = 1.0f / S;
        g_A[(b*Dd + d)*Pp + p] = mu * inv;
        g_I[(b*Dd + d)*Pp + p] = inv;
        acc += logf(S) + mu*mu*inv;
    }
    red[threadIdx.x] = acc; __syncthreads();
    for (int s = 128; s > 0; s >>= 1) {
        if (threadIdx.x < s) red[threadIdx.x] += red[threadIdx.x + s];
        __syncthreads();
    }
    if (threadIdx.x == 0)
        g_cst[b*Pp + p] = logf(g_pi[b*Pp + p]) - 0.5f * ((float)Dd * LOG2PI + red[0]);
}

__device__ __forceinline__ void load_xtile(float* xs, const float* __restrict__ dptr,
                                           int dc, int tid) {
    // xs tile: TN rows x DK cols, row stride XSTRIDE
    #pragma unroll
    for (int k = 0; k < 16; k++) {
        int lin = tid + k*256;
        int r = lin >> 5;
        int c = (lin & 31) * 4;
        float4 v = *(const float4*)(dptr + (size_t)r*Dd + dc + c);
        *(float4*)&xs[r*XSTRIDE + c] = v;
    }
}

__global__ void __launch_bounds__(256)
k_em(const float* __restrict__ data, const float* __restrict__ mask,
     float* __restrict__ out_qq) {
    extern __shared__ float smem[];
    float* xs  = smem;                       // TN * XSTRIDE
    float* as_ = smem + TN*XSTRIDE;          // DK * Pp   (A, layout [dk][p])
    float* is_ = as_ + DK*Pp;                // DK * Pp   (invS)
    float* qs  = is_ + DK*Pp;                // TN * Pp   (jll then qq)

    const int b  = blockIdx.y;
    const int n0 = blockIdx.x * TN;
    const int tid = threadIdx.x;
    const float* dptr = data + ((size_t)b*Nn + n0) * Dd;

    // ---------------- phase 1: s1 = x.(mu*invS), s2 = x^2.invS ----------------
    const int pp = tid & 7, p0 = pp * 2;
    const int nb = (tid >> 3) * 4;           // 4 consecutive n rows per thread

    float s1[4][2], s2[4][2];
    #pragma unroll
    for (int i = 0; i < 4; i++) { s1[i][0]=s1[i][1]=s2[i][0]=s2[i][1]=0.f; }

    for (int dc = 0; dc < Dd; dc += DK) {
        load_xtile(xs, dptr, dc, tid);
        #pragma unroll
        for (int k = 0; k < 2; k++) {
            int lin = tid + k*256;           // 0..511
            int dkr = lin >> 2, c = (lin & 3) * 4;
            size_t g = ((size_t)b*Dd + dc + dkr)*Pp + c;
            *(float4*)&as_[dkr*Pp + c] = *(const float4*)&g_A[g];
            *(float4*)&is_[dkr*Pp + c] = *(const float4*)&g_I[g];
        }
        __syncthreads();

        for (int dk = 0; dk < DK; dk += 4) {
            float xr[4][4];
            #pragma unroll
            for (int i = 0; i < 4; i++)
                *(float4*)xr[i] = *(const float4*)&xs[(nb+i)*XSTRIDE + dk];
            #pragma unroll
            for (int j = 0; j < 4; j++) {
                float2 av = *(const float2*)&as_[(dk+j)*Pp + p0];
                float2 iv = *(const float2*)&is_[(dk+j)*Pp + p0];
                #pragma unroll
                for (int i = 0; i < 4; i++) {
                    float x  = xr[i][j];
                    float x2 = x * x;
                    s1[i][0] = fmaf(x,  av.x, s1[i][0]);
                    s1[i][1] = fmaf(x,  av.y, s1[i][1]);
                    s2[i][0] = fmaf(x2, iv.x, s2[i][0]);
                    s2[i][1] = fmaf(x2, iv.y, s2[i][1]);
                }
            }
        }
        __syncthreads();
    }

    // jll into qs
    {
        float c0 = g_cst[b*Pp + p0];
        float c1 = g_cst[b*Pp + p0 + 1];
        #pragma unroll
        for (int i = 0; i < 4; i++) {
            qs[(nb+i)*Pp + p0    ] = c0 + s1[i][0] - 0.5f*s2[i][0];
            qs[(nb+i)*Pp + p0 + 1] = c1 + s1[i][1] - 0.5f*s2[i][1];
        }
    }
    __syncthreads();

    // ---------------- softmax -> qq ----------------
    if (tid < TN) {
        int n = tid;
        float v[Pp];
        float mx = -3.4e38f;
        #pragma unroll
        for (int k = 0; k < Pp; k++) { v[k] = qs[n*Pp + k]; mx = fmaxf(mx, v[k]); }
        float ssum = 0.f;
        #pragma unroll
        for (int k = 0; k < Pp; k++) { v[k] = expf(v[k] - mx); ssum += v[k]; }
        float w = mask[(size_t)b*Nn + n0 + n] / ssum;
        float* op = out_qq + ((size_t)(b*Nn + n0 + n)) * Pp;
        #pragma unroll
        for (int k = 0; k < Pp; k++) {
            float q = v[k] * w;
            qs[n*Pp + k] = q;
        }
        #pragma unroll
        for (int k = 0; k < Pp; k += 4) {
            float4 o = make_float4(qs[n*Pp+k], qs[n*Pp+k+1], qs[n*Pp+k+2], qs[n*Pp+k+3]);
            *(float4*)(op + k) = o;
        }
    }
    __syncthreads();

    // wsum partial
    if (tid < Pp) {
        float s = 0.f;
        for (int n = 0; n < TN; n++) s += qs[n*Pp + tid];
        atomicAdd(&g_wsum[b*Pp + tid], s);
    }
    __syncthreads();

    // ---------------- phase 2: wx += qq^T x, wxx += qq^T x^2 ----------------
    const int q0 = (tid & 7) * 2;            // 2 p per thread
    const int d0 = (tid >> 3) * 4;           // 4 d-cols per thread within chunk

    for (int dc = 0; dc < Dd; dc += DK) {
        load_xtile(xs, dptr, dc, tid);
        __syncthreads();

        float wx[2][4], wxx[2][4];
        #pragma unroll
        for (int a = 0; a < 2; a++)
            #pragma unroll
            for (int j = 0; j < 4; j++) { wx[a][j] = 0.f; wxx[a][j] = 0.f; }

        for (int n = 0; n < TN; n++) {
            float2 qv = *(const float2*)&qs[n*Pp + q0];
            float xa[4];
            *(float4*)xa = *(const float4*)&xs[n*XSTRIDE + d0];
            #pragma unroll
            for (int j = 0; j < 4; j++) {
                float x = xa[j], x2 = x*x;
                wx[0][j]  = fmaf(qv.x, x,  wx[0][j]);
                wx[1][j]  = fmaf(qv.y, x,  wx[1][j]);
                wxx[0][j] = fmaf(qv.x, x2, wxx[0][j]);
                wxx[1][j] = fmaf(qv.y, x2, wxx[1][j]);
            }
        }
        #pragma unroll
        for (int a = 0; a < 2; a++) {
            size_t base = ((size_t)(b*Pp + q0 + a))*Dd + dc + d0;
            #pragma unroll
            for (int j = 0; j < 4; j++) {
                atomicAdd(&g_wx[base + j],  wx[a][j]);
                atomicAdd(&g_wxx[base + j], wxx[a][j]);
            }
        }
        __syncthreads();
    }
}

__global__ void k_fin(const float* __restrict__ m) {
    int idx = blockIdx.x * 256 + threadIdx.x;    // < Bt*Pp*Dd
    int b = idx / (Pp*Dd);
    int r = idx % (Pp*Dd);
    int p = r / Dd;
    float ws = g_wsum[b*Pp + p] + 1.0f;          // tau = 1
    float mu = (g_wx[idx] + m[r]) / ws;
    float Sg = (g_wxx[idx] + g_mV[r]) / ws - mu*mu;
    g_mu[idx] = mu;
    g_Sg[idx] = Sg;
    g_wx[idx]  = 0.f;
    g_wxx[idx] = 0.f;
}

__global__ void k_pik() {
    int b = blockIdx.x, t = threadIdx.x;         // 32 threads
    float v = (t < Pp) ? (g_wsum[b*Pp + t] + 1.0f) : 0.f;
    float tot = v;
    #pragma unroll
    for (int o = 16; o > 0; o >>= 1) tot += __shfl_xor_sync(0xffffffffu, tot, o);
    if (t < Pp) {
        g_pi[b*Pp + t] = v / tot;
        g_wsum[b*Pp + t] = 0.f;
    }
}

__global__ void k_out(float* __restrict__ out) {
    int idx = blockIdx.x * 256 + threadIdx.x;    // < Bt*Pp*Dd
    out[Bt*Pp + idx] = g_mu[idx];
    out[Bt*Pp + Bt*Pp*Dd + idx] = g_Sg[idx];
    if (idx < Bt*Pp) out[idx] = g_pi[idx];
}

extern "C" void kernel_launch(void* const* d_in, const int* in_sizes, int n_in,
                              void* d_out, int out_size) {
    const float* data = (const float*)d_in[0];
    const float* mask = (const float*)d_in[1];
    const float* m    = (const float*)d_in[2];
    const float* V_   = (const float*)d_in[3];
    float* out = (float*)d_out;

    const int smem_bytes = (TN*XSTRIDE + 2*DK*Pp + TN*Pp) * (int)sizeof(float); // 92160
    cudaFuncSetAttribute(k_em, cudaFuncAttributeMaxDynamicSharedMemorySize, smem_bytes);

    const int qq_off = Bt*Pp + 2*Bt*Pp*Dd;       // 262272

    k_init<<<(Pp*Dd + 255)/256, 256>>>(m, V_);
    for (int it = 0; it < ITERS; it++) {
        k_prep<<<Bt*Pp, 256>>>();
        k_em<<<dim3(NT, Bt), 256, smem_bytes>>>(data, mask, out + qq_off);
        k_fin<<<(Bt*Pp*Dd)/256, 256>>>(m);
        k_pik<<<Bt, 32>>>();
    }
    k_out<<<(Bt*Pp*Dd)/256, 256>>>(out);
}